// round 1
// baseline (speedup 1.0000x reference)
#include <cuda_runtime.h>
#include <math.h>

// Problem constants: shape (4, 2, 16, 512, 512) fp32
#define R     8                   // B*C channels
#define NS    4194304             // 16*512*512 spatial per channel
#define NS4   (NS / 4)            // float4 count per channel
#define NBINS 256
#define BPC   512                 // blocks per channel for big passes
#define TPB   256

// ---------------- scratch (device globals — no allocation) ----------------
__device__ unsigned int       g_minkey[R];
__device__ unsigned int       g_maxkey[R];
__device__ unsigned int       g_hist[R][NBINS];
__device__ float              g_thr[R];
__device__ double             g_msum[R];   // masked sq-err sum
__device__ double             g_tot[R];    // total sq-err sum
__device__ double             g_inter[R];  // sum(soft_pred * mask)
__device__ double             g_ssum[R];   // sum(soft_pred)
__device__ unsigned long long g_fg[R];     // foreground count

// ordered-uint encoding of float for atomic min/max
__device__ __forceinline__ unsigned int fkey(float f) {
    unsigned int u = __float_as_uint(f);
    return (u & 0x80000000u) ? ~u : (u | 0x80000000u);
}
__device__ __forceinline__ float ikey(unsigned int k) {
    unsigned int u = (k & 0x80000000u) ? (k & 0x7FFFFFFFu) : ~k;
    return __uint_as_float(u);
}

// center of bin i, replicating reference fp32 ops exactly:
// edge_i = lo + span*(i/256); center = (edge_i + edge_{i+1}) * 0.5
__device__ __forceinline__ float bin_center(float lo, float span, int i) {
    float t0 = (float)i       * (1.0f / 256.0f);   // exact
    float t1 = (float)(i + 1) * (1.0f / 256.0f);   // exact
    float e0 = __fadd_rn(lo, __fmul_rn(span, t0));
    float e1 = __fadd_rn(lo, __fmul_rn(span, t1));
    return __fmul_rn(__fadd_rn(e0, e1), 0.5f);
}

// ---------------- kernel 0: zero scratch (runs every launch) ----------------
__global__ void k_init() {
    int t = threadIdx.x;
    for (int i = t; i < R * NBINS; i += blockDim.x)
        ((unsigned int*)g_hist)[i] = 0u;
    if (t < R) {
        g_minkey[t] = 0xFFFFFFFFu;
        g_maxkey[t] = 0u;
        g_msum[t] = 0.0; g_tot[t] = 0.0; g_inter[t] = 0.0; g_ssum[t] = 0.0;
        g_fg[t] = 0ull;
        g_thr[t] = 0.0f;
    }
}

// ---------------- kernel 1: per-channel min/max of target ----------------
__global__ void k_minmax(const float4* __restrict__ tgt) {
    const int c = blockIdx.y;
    const float4* base = tgt + (size_t)c * NS4;
    float lo =  INFINITY, hi = -INFINITY;
    for (int i = blockIdx.x * blockDim.x + threadIdx.x; i < NS4;
         i += gridDim.x * blockDim.x) {
        float4 v = base[i];
        lo = fminf(lo, fminf(fminf(v.x, v.y), fminf(v.z, v.w)));
        hi = fmaxf(hi, fmaxf(fmaxf(v.x, v.y), fmaxf(v.z, v.w)));
    }
    // warp reduce
    for (int o = 16; o > 0; o >>= 1) {
        lo = fminf(lo, __shfl_down_sync(0xFFFFFFFFu, lo, o));
        hi = fmaxf(hi, __shfl_down_sync(0xFFFFFFFFu, hi, o));
    }
    __shared__ float slo[8], shi[8];
    int w = threadIdx.x >> 5, lane = threadIdx.x & 31;
    if (lane == 0) { slo[w] = lo; shi[w] = hi; }
    __syncthreads();
    if (threadIdx.x == 0) {
        float l = slo[0], h = shi[0];
        for (int i = 1; i < 8; i++) { l = fminf(l, slo[i]); h = fmaxf(h, shi[i]); }
        atomicMin(&g_minkey[c], fkey(l));
        atomicMax(&g_maxkey[c], fkey(h));
    }
}

// ---------------- kernel 2: per-channel histogram ----------------
__global__ void k_hist(const float4* __restrict__ tgt) {
    const int c = blockIdx.y;
    __shared__ unsigned int sh[8][NBINS];   // per-warp sub-histograms
    __shared__ float s_lo, s_span;
    int tid = threadIdx.x, w = tid >> 5;
    for (int i = tid; i < 8 * NBINS; i += blockDim.x)
        ((unsigned int*)sh)[i] = 0u;
    if (tid == 0) {
        float lo = ikey(g_minkey[c]);
        float hi = ikey(g_maxkey[c]);
        float span = __fsub_rn(hi, lo);
        s_lo = lo;
        s_span = (span > 0.0f) ? span : 1.0f;   // safe_span
    }
    __syncthreads();
    const float lo = s_lo, span = s_span;
    const float4* base = tgt + (size_t)c * NS4;
    for (int i = blockIdx.x * blockDim.x + tid; i < NS4;
         i += gridDim.x * blockDim.x) {
        float4 v = base[i];
        #pragma unroll
        for (int j = 0; j < 4; j++) {
            float x = (j == 0) ? v.x : (j == 1) ? v.y : (j == 2) ? v.z : v.w;
            // exact replication: ((x - lo) / span) * 256, truncate, clip
            float q = __fmul_rn(__fdiv_rn(__fsub_rn(x, lo), span), 256.0f);
            int b = (int)q;
            b = min(max(b, 0), NBINS - 1);
            atomicAdd(&sh[w][b], 1u);
        }
    }
    __syncthreads();
    if (tid < NBINS) {
        unsigned int s = 0;
        #pragma unroll
        for (int k = 0; k < 8; k++) s += sh[k][tid];
        if (s) atomicAdd(&g_hist[c][tid], s);
    }
}

// ---------------- kernel 3: Otsu threshold per channel ----------------
__global__ void k_otsu() {
    const int c = blockIdx.x;
    const int tid = threadIdx.x;
    __shared__ float s_h[NBINS], s_ctr[NBINS], s_cs[NBINS], s_cm[NBINS];
    __shared__ float s_lo, s_span;
    __shared__ float rv[NBINS]; __shared__ int ri[NBINS];

    if (tid == 0) {
        float lo = ikey(g_minkey[c]);
        float hi = ikey(g_maxkey[c]);
        s_lo = lo;
        s_span = __fsub_rn(hi, lo);
    }
    __syncthreads();
    const float lo = s_lo, span = s_span;
    s_h[tid]   = (float)g_hist[c][tid];
    s_ctr[tid] = bin_center(lo, span, tid);
    __syncthreads();

    if (tid == 0) {   // fp32 sequential cumsum (256 steps, matches left-to-right)
        float cs = 0.0f, cm = 0.0f;
        for (int i = 0; i < NBINS; i++) {
            cs = __fadd_rn(cs, s_h[i]);                       // exact (ints < 2^24)
            cm = __fadd_rn(cm, __fmul_rn(s_h[i], s_ctr[i]));
            s_cs[i] = cs; s_cm[i] = cm;
        }
    }
    __syncthreads();
    const float total = s_cs[NBINS - 1];
    const float gmean = s_cm[NBINS - 1];

    // inter-class variance, fp32 replication
    float cs = s_cs[tid], cm = s_cm[tid];
    float A  = __fsub_rn(__fmul_rn(cm, total), __fmul_rn(gmean, cs));
    float dn = __fadd_rn(__fmul_rn(cs, __fsub_rn(total, cs)), 1e-10f);
    float iv = __fdiv_rn(__fmul_rn(A, A), dn);

    rv[tid] = iv; ri[tid] = tid;
    __syncthreads();
    for (int s = NBINS / 2; s > 0; s >>= 1) {   // argmax, first-index tie-break
        if (tid < s) {
            if (rv[tid + s] > rv[tid] ||
                (rv[tid + s] == rv[tid] && ri[tid + s] < ri[tid])) {
                rv[tid] = rv[tid + s]; ri[tid] = ri[tid + s];
            }
        }
        __syncthreads();
    }
    if (tid == 0) {
        float thr = s_ctr[ri[0]];
        g_thr[c] = (span > 0.0f) ? thr : lo;
    }
}

// ---------------- kernel 4: fused main reductions ----------------
__global__ void k_main(const float4* __restrict__ pred,
                       const float4* __restrict__ tgt) {
    const int c = blockIdx.y;
    const float thr = g_thr[c];
    const float4* pb = pred + (size_t)c * NS4;
    const float4* tb = tgt  + (size_t)c * NS4;

    float msum = 0.0f, tot = 0.0f, inter = 0.0f, ssum = 0.0f;
    int fg = 0;

    for (int i = blockIdx.x * blockDim.x + threadIdx.x; i < NS4;
         i += gridDim.x * blockDim.x) {
        float4 p4 = pb[i];
        float4 t4 = tb[i];
        #pragma unroll
        for (int j = 0; j < 4; j++) {
            float p = (j == 0) ? p4.x : (j == 1) ? p4.y : (j == 2) ? p4.z : p4.w;
            float t = (j == 0) ? t4.x : (j == 1) ? t4.y : (j == 2) ? t4.z : t4.w;
            bool m = (t >= thr);
            float d  = p - t;
            float se = d * d;
            tot += se;
            if (m) { msum += se; fg++; }
            // tunable sigmoid, k = -0.95:
            // raw = (x - k*x) / ((k - 2k|x|) + 1) ; clip [0,1]
            float ax  = fabsf(p);
            float num = p - (-0.95f) * p;                    // = 1.95*x form
            float den = (-0.95f - (-1.9f) * ax) + 1.0f;       // 0.05 + 1.9|x|
            float sp  = __saturatef(__fdividef(num, den));
            ssum += sp;
            if (m) inter += sp;
        }
    }
    // warp reduce
    for (int o = 16; o > 0; o >>= 1) {
        msum  += __shfl_down_sync(0xFFFFFFFFu, msum,  o);
        tot   += __shfl_down_sync(0xFFFFFFFFu, tot,   o);
        inter += __shfl_down_sync(0xFFFFFFFFu, inter, o);
        ssum  += __shfl_down_sync(0xFFFFFFFFu, ssum,  o);
        fg    += __shfl_down_sync(0xFFFFFFFFu, fg,    o);
    }
    __shared__ float  s0[8], s1[8], s2[8], s3[8];
    __shared__ int    s4[8];
    int w = threadIdx.x >> 5, lane = threadIdx.x & 31;
    if (lane == 0) { s0[w]=msum; s1[w]=tot; s2[w]=inter; s3[w]=ssum; s4[w]=fg; }
    __syncthreads();
    if (threadIdx.x == 0) {
        double a=0, b=0, cI=0, dS=0; long long f=0;
        #pragma unroll
        for (int k = 0; k < 8; k++) { a+=s0[k]; b+=s1[k]; cI+=s2[k]; dS+=s3[k]; f+=s4[k]; }
        atomicAdd(&g_msum[c],  a);
        atomicAdd(&g_tot[c],   b);
        atomicAdd(&g_inter[c], cI);
        atomicAdd(&g_ssum[c],  dS);
        atomicAdd(&g_fg[c], (unsigned long long)f);
    }
}

// ---------------- kernel 5: combine to scalar ----------------
__global__ void k_combine(float* __restrict__ out) {
    if (threadIdx.x != 0 || blockIdx.x != 0) return;
    double mse_sum = 0.0, dice_sum = 0.0;
    int nmask = 0;
    for (int c = 0; c < R; c++) {
        double fg = (double)g_fg[c];
        bool has = fg > 0.0;
        double cm = has ? g_msum[c] / (fg + 1e-6)
                        : g_tot[c] / (double)NS;
        mse_sum += cm;
        if (has) {
            double cd = 1.0 - 2.0 * g_inter[c] / (g_ssum[c] + fg + 1e-6);
            dice_sum += cd;
            nmask++;
        }
    }
    double masked_mse = mse_sum / (double)R;
    double dice = (nmask > 0) ? dice_sum / (double)nmask : 0.0;
    out[0] = (float)(0.5 * masked_mse + 0.5 * dice);
}

// ---------------- launch ----------------
extern "C" void kernel_launch(void* const* d_in, const int* in_sizes, int n_in,
                              void* d_out, int out_size) {
    const float4* pred = (const float4*)d_in[0];
    const float4* tgt  = (const float4*)d_in[1];
    float* out = (float*)d_out;

    dim3 grid(BPC, R);
    k_init<<<1, 256>>>();
    k_minmax<<<grid, TPB>>>(tgt);
    k_hist<<<grid, TPB>>>(tgt);
    k_otsu<<<R, NBINS>>>();
    k_main<<<grid, TPB>>>(pred, tgt);
    k_combine<<<1, 32>>>(out);
}

// round 2
// speedup vs baseline: 1.0111x; 1.0111x over previous
#include <cuda_runtime.h>
#include <math.h>

// Problem constants: shape (4, 2, 16, 512, 512) fp32
#define R     8                   // B*C channels
#define NS    4194304             // 16*512*512 spatial per channel
#define NS4   (NS / 4)            // float4 count per channel
#define NBINS 256
#define BPC   512                 // blocks per channel for big passes
#define TPB   256

// ---------------- scratch (device globals — no allocation) ----------------
__device__ unsigned int       g_minkey[R];
__device__ unsigned int       g_maxkey[R];
__device__ unsigned int       g_hist[R][NBINS];
__device__ float              g_thr[R];
__device__ double             g_msum[R];   // masked sq-err sum
__device__ double             g_tot[R];    // total sq-err sum
__device__ double             g_inter[R];  // sum(soft_pred * mask)
__device__ double             g_ssum[R];   // sum(soft_pred)
__device__ unsigned long long g_fg[R];     // foreground count
__device__ unsigned int       g_cnt_hist[R];  // finished-block counters
__device__ unsigned int       g_cnt_main;

// ordered-uint encoding of float for atomic min/max
__device__ __forceinline__ unsigned int fkey(float f) {
    unsigned int u = __float_as_uint(f);
    return (u & 0x80000000u) ? ~u : (u | 0x80000000u);
}
__device__ __forceinline__ float ikey(unsigned int k) {
    unsigned int u = (k & 0x80000000u) ? (k & 0x7FFFFFFFu) : ~k;
    return __uint_as_float(u);
}

// center of bin i, replicating reference fp32 ops exactly
__device__ __forceinline__ float bin_center(float lo, float span, int i) {
    float t0 = (float)i       * (1.0f / 256.0f);   // exact
    float t1 = (float)(i + 1) * (1.0f / 256.0f);   // exact
    float e0 = __fadd_rn(lo, __fmul_rn(span, t0));
    float e1 = __fadd_rn(lo, __fmul_rn(span, t1));
    return __fmul_rn(__fadd_rn(e0, e1), 0.5f);
}

// ---------------- kernel 0: zero scratch (runs every launch) ----------------
__global__ void k_init() {
    int t = threadIdx.x;
    for (int i = t; i < R * NBINS; i += blockDim.x)
        ((unsigned int*)g_hist)[i] = 0u;
    if (t < R) {
        g_minkey[t] = 0xFFFFFFFFu;
        g_maxkey[t] = 0u;
        g_msum[t] = 0.0; g_tot[t] = 0.0; g_inter[t] = 0.0; g_ssum[t] = 0.0;
        g_fg[t] = 0ull;
        g_thr[t] = 0.0f;
        g_cnt_hist[t] = 0u;
    }
    if (t == R) g_cnt_main = 0u;
}

// ---------------- kernel 1: per-channel min/max of target (forward) --------
__global__ void k_minmax(const float4* __restrict__ tgt) {
    const int c = blockIdx.y;
    const float4* base = tgt + (size_t)c * NS4;
    float lo =  INFINITY, hi = -INFINITY;
    for (int i = blockIdx.x * blockDim.x + threadIdx.x; i < NS4;
         i += gridDim.x * blockDim.x) {
        float4 v = base[i];
        lo = fminf(lo, fminf(fminf(v.x, v.y), fminf(v.z, v.w)));
        hi = fmaxf(hi, fmaxf(fmaxf(v.x, v.y), fmaxf(v.z, v.w)));
    }
    for (int o = 16; o > 0; o >>= 1) {
        lo = fminf(lo, __shfl_down_sync(0xFFFFFFFFu, lo, o));
        hi = fmaxf(hi, __shfl_down_sync(0xFFFFFFFFu, hi, o));
    }
    __shared__ float slo[8], shi[8];
    int w = threadIdx.x >> 5, lane = threadIdx.x & 31;
    if (lane == 0) { slo[w] = lo; shi[w] = hi; }
    __syncthreads();
    if (threadIdx.x == 0) {
        float l = slo[0], h = shi[0];
        for (int i = 1; i < 8; i++) { l = fminf(l, slo[i]); h = fmaxf(h, shi[i]); }
        atomicMin(&g_minkey[c], fkey(l));
        atomicMax(&g_maxkey[c], fkey(h));
    }
}

// ------- kernel 2: histogram (REVERSE traversal for L2 reuse) + fused Otsu -
__global__ void k_hist(const float4* __restrict__ tgt) {
    const int c = blockIdx.y;
    __shared__ unsigned int sh[8][NBINS];   // per-warp sub-histograms
    __shared__ float s_lo, s_span_safe, s_span_raw;
    int tid = threadIdx.x, w = tid >> 5;
    for (int i = tid; i < 8 * NBINS; i += blockDim.x)
        ((unsigned int*)sh)[i] = 0u;
    if (tid == 0) {
        float lo = ikey(g_minkey[c]);
        float hi = ikey(g_maxkey[c]);
        float span = __fsub_rn(hi, lo);
        s_lo = lo;
        s_span_raw = span;
        s_span_safe = (span > 0.0f) ? span : 1.0f;
    }
    __syncthreads();
    const float lo = s_lo, span = s_span_safe;
    const float4* base = tgt + (size_t)c * NS4;
    for (int i = blockIdx.x * blockDim.x + tid; i < NS4;
         i += gridDim.x * blockDim.x) {
        float4 v = base[NS4 - 1 - i];       // reverse: hit L2 left by k_minmax
        #pragma unroll
        for (int j = 0; j < 4; j++) {
            float x = (j == 0) ? v.x : (j == 1) ? v.y : (j == 2) ? v.z : v.w;
            float q = __fmul_rn(__fdiv_rn(__fsub_rn(x, lo), span), 256.0f);
            int b = (int)q;
            b = min(max(b, 0), NBINS - 1);
            atomicAdd(&sh[w][b], 1u);
        }
    }
    __syncthreads();
    if (tid < NBINS) {
        unsigned int s = 0;
        #pragma unroll
        for (int k = 0; k < 8; k++) s += sh[k][tid];
        if (s) atomicAdd(&g_hist[c][tid], s);
    }

    // ---- last block of this channel computes the Otsu threshold ----
    __threadfence();
    __shared__ bool is_last;
    if (tid == 0)
        is_last = (atomicAdd(&g_cnt_hist[c], 1u) == (unsigned)(BPC - 1));
    __syncthreads();
    if (!is_last) return;

    __shared__ float s_h[NBINS], s_hm[NBINS], s_ctr[NBINS];
    __shared__ float s_cs[NBINS], s_cm[NBINS];
    __shared__ float rv[NBINS]; __shared__ int ri[NBINS];

    const float span_raw = s_span_raw;
    float h   = (float)__ldcg(&g_hist[c][tid]);   // bypass L1 (other blocks wrote via L2)
    float ctr = bin_center(lo, span_raw, tid);
    s_h[tid] = h; s_ctr[tid] = ctr; s_hm[tid] = __fmul_rn(h, ctr);
    __syncthreads();

    if (tid == 0) {   // two independent 4-cyc FADD chains, fully unrolled
        float cs = 0.0f, cm = 0.0f;
        #pragma unroll
        for (int i = 0; i < NBINS; i++) {
            cs = __fadd_rn(cs, s_h[i]);
            cm = __fadd_rn(cm, s_hm[i]);
            s_cs[i] = cs; s_cm[i] = cm;
        }
    }
    __syncthreads();
    const float total = s_cs[NBINS - 1];
    const float gmean = s_cm[NBINS - 1];

    float cs = s_cs[tid], cm = s_cm[tid];
    float A  = __fsub_rn(__fmul_rn(cm, total), __fmul_rn(gmean, cs));
    float dn = __fadd_rn(__fmul_rn(cs, __fsub_rn(total, cs)), 1e-10f);
    float iv = __fdiv_rn(__fmul_rn(A, A), dn);

    rv[tid] = iv; ri[tid] = tid;
    __syncthreads();
    for (int s = NBINS / 2; s > 0; s >>= 1) {   // argmax, first-index tie-break
        if (tid < s) {
            if (rv[tid + s] > rv[tid] ||
                (rv[tid + s] == rv[tid] && ri[tid + s] < ri[tid])) {
                rv[tid] = rv[tid + s]; ri[tid] = ri[tid + s];
            }
        }
        __syncthreads();
    }
    if (tid == 0) {
        float thr = s_ctr[ri[0]];
        g_thr[c] = (span_raw > 0.0f) ? thr : lo;
    }
}

// ------- kernel 3: fused main reductions (forward) + fused combine ---------
__global__ void k_main(const float4* __restrict__ pred,
                       const float4* __restrict__ tgt,
                       float* __restrict__ out) {
    const int c = blockIdx.y;
    const float thr = g_thr[c];
    const float4* pb = pred + (size_t)c * NS4;
    const float4* tb = tgt  + (size_t)c * NS4;

    float msum = 0.0f, tot = 0.0f, inter = 0.0f, ssum = 0.0f;
    int fg = 0;

    for (int i = blockIdx.x * blockDim.x + threadIdx.x; i < NS4;
         i += gridDim.x * blockDim.x) {
        float4 p4 = __ldcs(&pb[i]);   // streaming: read-once, don't evict target
        float4 t4 = __ldcs(&tb[i]);
        #pragma unroll
        for (int j = 0; j < 4; j++) {
            float p = (j == 0) ? p4.x : (j == 1) ? p4.y : (j == 2) ? p4.z : p4.w;
            float t = (j == 0) ? t4.x : (j == 1) ? t4.y : (j == 2) ? t4.z : t4.w;
            bool m = (t >= thr);
            float d  = p - t;
            float se = d * d;
            tot += se;
            if (m) { msum += se; fg++; }
            // tunable sigmoid, k = -0.95
            float ax  = fabsf(p);
            float num = p - (-0.95f) * p;                 // 1.95*x
            float den = (-0.95f - (-1.9f) * ax) + 1.0f;   // 0.05 + 1.9|x|
            float sp  = __saturatef(__fdividef(num, den));
            ssum += sp;
            if (m) inter += sp;
        }
    }
    for (int o = 16; o > 0; o >>= 1) {
        msum  += __shfl_down_sync(0xFFFFFFFFu, msum,  o);
        tot   += __shfl_down_sync(0xFFFFFFFFu, tot,   o);
        inter += __shfl_down_sync(0xFFFFFFFFu, inter, o);
        ssum  += __shfl_down_sync(0xFFFFFFFFu, ssum,  o);
        fg    += __shfl_down_sync(0xFFFFFFFFu, fg,    o);
    }
    __shared__ float  s0[8], s1[8], s2[8], s3[8];
    __shared__ int    s4[8];
    int w = threadIdx.x >> 5, lane = threadIdx.x & 31;
    if (lane == 0) { s0[w]=msum; s1[w]=tot; s2[w]=inter; s3[w]=ssum; s4[w]=fg; }
    __syncthreads();
    __shared__ bool is_last;
    if (threadIdx.x == 0) {
        double a=0, b=0, cI=0, dS=0; long long f=0;
        #pragma unroll
        for (int k = 0; k < 8; k++) { a+=s0[k]; b+=s1[k]; cI+=s2[k]; dS+=s3[k]; f+=s4[k]; }
        atomicAdd(&g_msum[c],  a);
        atomicAdd(&g_tot[c],   b);
        atomicAdd(&g_inter[c], cI);
        atomicAdd(&g_ssum[c],  dS);
        atomicAdd(&g_fg[c], (unsigned long long)f);
        __threadfence();
        is_last = (atomicAdd(&g_cnt_main, 1u) == (unsigned)(BPC * R - 1));
    }
    __syncthreads();
    if (!is_last || threadIdx.x != 0) return;

    // ---- globally-last block: combine to scalar ----
    double mse_sum = 0.0, dice_sum = 0.0;
    int nmask = 0;
    for (int ch = 0; ch < R; ch++) {
        double fgc = (double)__ldcg(&g_fg[ch]);
        bool has = fgc > 0.0;
        double cmse = has ? __ldcg(&g_msum[ch]) / (fgc + 1e-6)
                          : __ldcg(&g_tot[ch]) / (double)NS;
        mse_sum += cmse;
        if (has) {
            double cd = 1.0 - 2.0 * __ldcg(&g_inter[ch]) /
                                    (__ldcg(&g_ssum[ch]) + fgc + 1e-6);
            dice_sum += cd;
            nmask++;
        }
    }
    double masked_mse = mse_sum / (double)R;
    double dice = (nmask > 0) ? dice_sum / (double)nmask : 0.0;
    out[0] = (float)(0.5 * masked_mse + 0.5 * dice);
}

// ---------------- launch ----------------
extern "C" void kernel_launch(void* const* d_in, const int* in_sizes, int n_in,
                              void* d_out, int out_size) {
    const float4* pred = (const float4*)d_in[0];
    const float4* tgt  = (const float4*)d_in[1];
    float* out = (float*)d_out;

    dim3 grid(BPC, R);
    k_init<<<1, 256>>>();
    k_minmax<<<grid, TPB>>>(tgt);
    k_hist<<<grid, TPB>>>(tgt);
    k_main<<<grid, TPB>>>(pred, tgt, out);
}